// round 3
// baseline (speedup 1.0000x reference)
#include <cuda_runtime.h>

// Problem constants
#define NM 100000
#define NT 100000
#define NE 400000
#define DD 128
#define K2 256   // concat K dim: [agg | x_dst]

#define CDIV(a,b) (((a)+(b)-1)/(b))

// ---------------- scratch (static __device__ allocations, 16B-aligned) ----
__device__ float4 g_agg_t[(size_t)NT * DD / 4];
__device__ float4 g_agg_m[(size_t)NM * DD / 4];
__device__ float4 g_bm0[(size_t)NM * DD / 4];
__device__ float4 g_bm1[(size_t)NM * DD / 4];
__device__ float4 g_bt0[(size_t)NT * DD / 4];
__device__ float4 g_bt1[(size_t)NT * DD / 4];
__device__ float4 g_inv_t[NT / 4];
__device__ float4 g_inv_m[NM / 4];
__device__ float4 g_Bext[3 * 2 * K2 * DD / 4];   // [layer][type][k][j]
__device__ int    g_e32_mt[2 * NE];
__device__ int    g_e32_tm[2 * NE];
__device__ int    g_is32;                        // 1 if edge buffers are int32

// ---------------- edge dtype detect + convert ----------------
__global__ void detect_reset() { g_is32 = 0; }

// Scan first 2E 32-bit words (safe for both dtypes). For int64 edges with
// values < 2^31, every odd 32-bit word is 0. For int32 edges, odd words are
// random indices -> OR is nonzero with overwhelming probability.
__global__ void detect_kernel(const unsigned* __restrict__ p) {
    int i = blockIdx.x * blockDim.x + threadIdx.x;
    unsigned v = 0;
    for (int w = i * 2 + 1; w < 2 * NE; w += gridDim.x * blockDim.x * 2)
        v |= p[w];
    if (__syncthreads_or(v != 0) && threadIdx.x == 0) atomicExch(&g_is32, 1);
}

__global__ void convert_kernel(const void* __restrict__ e, int* __restrict__ out) {
    int i = blockIdx.x * blockDim.x + threadIdx.x;
    if (i >= 2 * NE) return;
    int v;
    if (g_is32) v = ((const int*)e)[i];
    else        v = (int)((const long long*)e)[i];
    // clamp: turns any residual index bug into a wrong answer, not an IMA
    out[i] = min(max(v, 0), (NM < NT ? NM : NT) - 1);
}

// ---------------- small utility kernels ----------------
__global__ void zero_kernel(float4* p, int n4) {
    int i = blockIdx.x * blockDim.x + threadIdx.x;
    int stride = gridDim.x * blockDim.x;
    float4 z = make_float4(0.f, 0.f, 0.f, 0.f);
    for (; i < n4; i += stride) p[i] = z;
}

// Build B_ext[lt][k][j] = (k < D ? Wl[lt][j][k] : Wr[lt][j][k-D])
__global__ void prep_weights(const float* __restrict__ Wl,
                             const float* __restrict__ Wr,
                             float* __restrict__ Bext) {
    int i = blockIdx.x * blockDim.x + threadIdx.x;
    if (i >= 3 * 2 * K2 * DD) return;
    int j  = i % DD;
    int k  = (i / DD) % K2;
    int lt = i / (DD * K2);
    float v = (k < DD) ? Wl[((size_t)lt * DD + j) * DD + k]
                       : Wr[((size_t)lt * DD + j) * DD + (k - DD)];
    Bext[i] = v;
}

__global__ void count_kernel(const int* __restrict__ edge,
                             float* __restrict__ cnt) {
    int i = blockIdx.x * blockDim.x + threadIdx.x;
    if (i < NE) atomicAdd(&cnt[edge[NE + i]], 1.0f);
}

__global__ void invert_kernel(float* __restrict__ c, int n) {
    int i = blockIdx.x * blockDim.x + threadIdx.x;
    if (i < n) c[i] = 1.0f / fmaxf(c[i], 1.0f);
}

// ---------------- scatter: warp per edge, float4 per lane ----------------
__global__ void scatter_kernel(const float* __restrict__ xsrc,
                               const int* __restrict__ edge,
                               float* __restrict__ agg) {
    int w = (blockIdx.x * blockDim.x + threadIdx.x) >> 5;
    int lane = threadIdx.x & 31;
    if (w >= NE) return;
    int src = edge[w];
    int dst = edge[NE + w];
    float4 v = ((const float4*)(xsrc + (size_t)src * DD))[lane];
    float* a = agg + (size_t)dst * DD + lane * 4;
    atomicAdd(a + 0, v.x);
    atomicAdd(a + 1, v.y);
    atomicAdd(a + 2, v.z);
    atomicAdd(a + 3, v.w);
}

// ---------------- fused SAGE GEMM ----------------
// C[i, j] = sum_k<128 (agg[i,k]*inv[i]) * B[k,j] + sum_k x[i,k] * B[128+k,j] + bias[j]
__global__ void __launch_bounds__(256, 2)
gemm_sage(const float* __restrict__ Aagg, const float* __restrict__ inv,
          const float* __restrict__ Xdst, const float* __restrict__ B,
          const float* __restrict__ bias, float* __restrict__ Cout,
          int nRows, int relu) {
    __shared__ float As[16][132];   // [kk][row], padded stride
    __shared__ float Bs[16][128];   // [kk][col]

    const int tid = threadIdx.x;
    const int i0 = (tid >> 4) * 8;
    const int j0 = (tid & 15) * 8;
    const int rowBase = blockIdx.x * 128;

    float acc[8][8];
#pragma unroll
    for (int i = 0; i < 8; i++)
#pragma unroll
        for (int j = 0; j < 8; j++) acc[i][j] = 0.f;

    for (int kt = 0; kt < K2; kt += 16) {
#pragma unroll
        for (int p = 0; p < 2; p++) {
            int f = tid + p * 256;
            int r = f >> 2;
            int q = f & 3;
            int gr = rowBase + r;
            if (gr >= nRows) gr = nRows - 1;
            int kg = kt + q * 4;
            float s;
            const float* src;
            if (kg < DD) { src = Aagg + (size_t)gr * DD + kg; s = inv[gr]; }
            else         { src = Xdst + (size_t)gr * DD + (kg - DD); s = 1.0f; }
            float4 v = *(const float4*)src;
            As[q * 4 + 0][r] = v.x * s;
            As[q * 4 + 1][r] = v.y * s;
            As[q * 4 + 2][r] = v.z * s;
            As[q * 4 + 3][r] = v.w * s;
        }
#pragma unroll
        for (int p = 0; p < 2; p++) {
            int f = tid + p * 256;
            int kr = f >> 5;
            int c  = f & 31;
            float4 v = *(const float4*)(B + (size_t)(kt + kr) * DD + c * 4);
            *(float4*)&Bs[kr][c * 4] = v;
        }
        __syncthreads();

#pragma unroll
        for (int kk = 0; kk < 16; kk++) {
            float a[8], b[8];
#pragma unroll
            for (int i = 0; i < 8; i++) a[i] = As[kk][i0 + i];
            float4 b0 = *(const float4*)&Bs[kk][j0];
            float4 b1 = *(const float4*)&Bs[kk][j0 + 4];
            b[0] = b0.x; b[1] = b0.y; b[2] = b0.z; b[3] = b0.w;
            b[4] = b1.x; b[5] = b1.y; b[6] = b1.z; b[7] = b1.w;
#pragma unroll
            for (int i = 0; i < 8; i++)
#pragma unroll
                for (int j = 0; j < 8; j++) acc[i][j] += a[i] * b[j];
        }
        __syncthreads();
    }

    float bj[8];
#pragma unroll
    for (int j = 0; j < 8; j++) bj[j] = bias[j0 + j];

#pragma unroll
    for (int i = 0; i < 8; i++) {
        int gr = rowBase + i0 + i;
        if (gr < nRows) {
            float v0 = acc[i][0] + bj[0], v1 = acc[i][1] + bj[1];
            float v2 = acc[i][2] + bj[2], v3 = acc[i][3] + bj[3];
            float v4 = acc[i][4] + bj[4], v5 = acc[i][5] + bj[5];
            float v6 = acc[i][6] + bj[6], v7 = acc[i][7] + bj[7];
            if (relu) {
                v0 = fmaxf(v0, 0.f); v1 = fmaxf(v1, 0.f);
                v2 = fmaxf(v2, 0.f); v3 = fmaxf(v3, 0.f);
                v4 = fmaxf(v4, 0.f); v5 = fmaxf(v5, 0.f);
                v6 = fmaxf(v6, 0.f); v7 = fmaxf(v7, 0.f);
            }
            float4* dst = (float4*)(Cout + (size_t)gr * DD + j0);
            dst[0] = make_float4(v0, v1, v2, v3);
            dst[1] = make_float4(v4, v5, v6, v7);
        }
    }
}

// ---------------- launch ----------------
extern "C" void kernel_launch(void* const* d_in, const int* in_sizes, int n_in,
                              void* d_out, int out_size) {
    const float* x_m = (const float*)d_in[0];
    const float* x_t = (const float*)d_in[1];
    const float* Wl  = (const float*)d_in[2];
    const float* bl  = (const float*)d_in[3];
    const float* Wr  = (const float*)d_in[4];
    const void*  e_mt = d_in[5];
    const void*  e_tm = d_in[6];
    float* out = (float*)d_out;

    float *agg_t, *agg_m, *bm0, *bm1, *bt0, *bt1, *inv_t, *inv_m, *Bext;
    int *e32_mt, *e32_tm;
    cudaGetSymbolAddress((void**)&agg_t, g_agg_t);
    cudaGetSymbolAddress((void**)&agg_m, g_agg_m);
    cudaGetSymbolAddress((void**)&bm0, g_bm0);
    cudaGetSymbolAddress((void**)&bm1, g_bm1);
    cudaGetSymbolAddress((void**)&bt0, g_bt0);
    cudaGetSymbolAddress((void**)&bt1, g_bt1);
    cudaGetSymbolAddress((void**)&inv_t, g_inv_t);
    cudaGetSymbolAddress((void**)&inv_m, g_inv_m);
    cudaGetSymbolAddress((void**)&Bext, g_Bext);
    cudaGetSymbolAddress((void**)&e32_mt, g_e32_mt);
    cudaGetSymbolAddress((void**)&e32_tm, g_e32_tm);

    // ---- edge dtype detection + conversion to int32 ----
    detect_reset<<<1, 1>>>();
    detect_kernel<<<256, 256>>>((const unsigned*)e_mt);
    convert_kernel<<<CDIV(2 * NE, 256), 256>>>(e_mt, e32_mt);
    convert_kernel<<<CDIV(2 * NE, 256), 256>>>(e_tm, e32_tm);

    // weight transpose/concat
    prep_weights<<<CDIV(3 * 2 * K2 * DD, 256), 256>>>(Wl, Wr, Bext);

    // per-destination inverse mean counts (edge-only, reused for all layers)
    zero_kernel<<<128, 256>>>((float4*)inv_t, NT / 4);
    zero_kernel<<<128, 256>>>((float4*)inv_m, NM / 4);
    count_kernel<<<CDIV(NE, 256), 256>>>(e32_mt, inv_t);
    count_kernel<<<CDIV(NE, 256), 256>>>(e32_tm, inv_m);
    invert_kernel<<<CDIV(NT, 256), 256>>>(inv_t, NT);
    invert_kernel<<<CDIV(NM, 256), 256>>>(inv_m, NM);

    const float* xm_cur = x_m;
    const float* xt_cur = x_t;
    float* out_m = out;
    float* out_t = out + (size_t)NM * DD;

    const int scatterBlocks = CDIV(NE * 32, 256);
    const int aggT4 = NT * DD / 4;
    const int aggM4 = NM * DD / 4;

    for (int layer = 0; layer < 3; layer++) {
        float* xt_next = (layer == 2) ? out_t : ((layer == 0) ? bt0 : bt1);
        float* xm_next = (layer == 2) ? out_m : ((layer == 0) ? bm0 : bm1);
        int relu = (layer < 2) ? 1 : 0;

        // edge type 0: musicians -> tracks
        zero_kernel<<<4096, 256>>>((float4*)agg_t, aggT4);
        scatter_kernel<<<scatterBlocks, 256>>>(xm_cur, e32_mt, agg_t);
        // edge type 1: tracks -> musicians
        zero_kernel<<<4096, 256>>>((float4*)agg_m, aggM4);
        scatter_kernel<<<scatterBlocks, 256>>>(xt_cur, e32_tm, agg_m);

        gemm_sage<<<CDIV(NT, 128), 256>>>(
            agg_t, inv_t, xt_cur,
            Bext + (size_t)(layer * 2 + 0) * K2 * DD,
            bl + (size_t)(layer * 2 + 0) * DD,
            xt_next, NT, relu);
        gemm_sage<<<CDIV(NM, 128), 256>>>(
            agg_m, inv_m, xm_cur,
            Bext + (size_t)(layer * 2 + 1) * K2 * DD,
            bl + (size_t)(layer * 2 + 1) * DD,
            xm_next, NM, relu);

        xm_cur = xm_next;
        xt_cur = xt_next;
    }
}

// round 4
// speedup vs baseline: 2.1485x; 2.1485x over previous
#include <cuda_runtime.h>
#include <cstdint>

// Problem constants
#define NM 100000
#define NT 100000
#define NE 400000
#define DD 128
#define K2 256   // concat K dim: [agg | x_dst]

#define CDIV(a,b) (((a)+(b)-1)/(b))

// ---------------- scratch (static __device__ allocations, 16B-aligned) ----
__device__ float4 g_agg_t[(size_t)NT * DD / 4];
__device__ float4 g_agg_m[(size_t)NM * DD / 4];
__device__ float4 g_bm0[(size_t)NM * DD / 4];
__device__ float4 g_bm1[(size_t)NM * DD / 4];
__device__ float4 g_bt0[(size_t)NT * DD / 4];
__device__ float4 g_bt1[(size_t)NT * DD / 4];
__device__ float4 g_inv_t[NT / 4];
__device__ float4 g_inv_m[NM / 4];
__device__ float4 g_Bext[3 * 2 * K2 * DD / 4];   // [layer][type][k][j]
__device__ int    g_e32_mt[2 * NE];
__device__ int    g_e32_tm[2 * NE];
__device__ int    g_is32;                        // 1 if edge buffers are int32

// ---------------- edge dtype detect + convert ----------------
__global__ void detect_reset() { g_is32 = 0; }

__global__ void detect_kernel(const unsigned* __restrict__ p) {
    int i = blockIdx.x * blockDim.x + threadIdx.x;
    unsigned v = 0;
    for (int w = i * 2 + 1; w < 2 * NE; w += gridDim.x * blockDim.x * 2)
        v |= p[w];
    if (__syncthreads_or(v != 0) && threadIdx.x == 0) atomicExch(&g_is32, 1);
}

__global__ void convert_kernel(const void* __restrict__ e, int* __restrict__ out) {
    int i = blockIdx.x * blockDim.x + threadIdx.x;
    if (i >= 2 * NE) return;
    int v;
    if (g_is32) v = ((const int*)e)[i];
    else        v = (int)((const long long*)e)[i];
    out[i] = min(max(v, 0), (NM < NT ? NM : NT) - 1);
}

// ---------------- small utility kernels ----------------
__global__ void zero_kernel(float4* p, int n4) {
    int i = blockIdx.x * blockDim.x + threadIdx.x;
    int stride = gridDim.x * blockDim.x;
    float4 z = make_float4(0.f, 0.f, 0.f, 0.f);
    for (; i < n4; i += stride) p[i] = z;
}

// Build B_ext[lt][k][j] = (k < D ? Wl[lt][j][k] : Wr[lt][j][k-D])
__global__ void prep_weights(const float* __restrict__ Wl,
                             const float* __restrict__ Wr,
                             float* __restrict__ Bext) {
    int i = blockIdx.x * blockDim.x + threadIdx.x;
    if (i >= 3 * 2 * K2 * DD) return;
    int j  = i % DD;
    int k  = (i / DD) % K2;
    int lt = i / (DD * K2);
    float v = (k < DD) ? Wl[((size_t)lt * DD + j) * DD + k]
                       : Wr[((size_t)lt * DD + j) * DD + (k - DD)];
    Bext[i] = v;
}

__global__ void count_kernel(const int* __restrict__ edge,
                             float* __restrict__ cnt) {
    int i = blockIdx.x * blockDim.x + threadIdx.x;
    if (i < NE) atomicAdd(&cnt[edge[NE + i]], 1.0f);
}

__global__ void invert_kernel(float* __restrict__ c, int n) {
    int i = blockIdx.x * blockDim.x + threadIdx.x;
    if (i < n) c[i] = 1.0f / fmaxf(c[i], 1.0f);
}

// ---------------- scatter: warp per edge, red.v4 per lane ----------------
__global__ void scatter_kernel(const float* __restrict__ xsrc,
                               const int* __restrict__ edge,
                               float* __restrict__ agg) {
    int w = (blockIdx.x * blockDim.x + threadIdx.x) >> 5;
    int lane = threadIdx.x & 31;
    if (w >= NE) return;
    int src = edge[w];
    int dst = edge[NE + w];
    float4 v = ((const float4*)(xsrc + (size_t)src * DD))[lane];
    float* a = agg + (size_t)dst * DD + lane * 4;
    asm volatile("red.global.add.v4.f32 [%0], {%1,%2,%3,%4};"
                 :: "l"(a), "f"(v.x), "f"(v.y), "f"(v.z), "f"(v.w)
                 : "memory");
}

// ---------------- tf32 tensor-core fused SAGE GEMM ----------------
// C[i,j] = sum_{k<128} (agg[i,k]*inv[i])*B[k,j] + sum_k x[i,k]*B[128+k,j] + bias[j]
// Block: 256 thr, tile 128(M)x128(N), BK=32. 8 warps, each 64x32 via m16n8k8 tf32.
__device__ __forceinline__ uint32_t f2tf32(float f) {
    uint32_t r;
    asm("cvt.rna.tf32.f32 %0, %1;" : "=r"(r) : "f"(f));
    return r;
}

__global__ void __launch_bounds__(256)
gemm_sage_tc(const float* __restrict__ Aagg, const float* __restrict__ inv,
             const float* __restrict__ Xdst, const float* __restrict__ B,
             const float* __restrict__ bias, float* __restrict__ Cout,
             int nRows, int relu) {
    __shared__ uint32_t As[128][36];    // [row][k]  pad 36: bank = 4g+t, bijective
    __shared__ uint32_t Bs[32][136];    // [k][col]  pad 136: bank = 8t+g, bijective

    const int tid  = threadIdx.x;
    const int wid  = tid >> 5;
    const int lane = tid & 31;
    const int g    = lane >> 2;     // group id 0..7
    const int t    = lane & 3;      // thread-in-group 0..3
    const int m0   = (wid & 1) * 64;    // warp M offset
    const int n0   = (wid >> 1) * 32;   // warp N offset
    const int rowBase = blockIdx.x * 128;

    float acc[4][4][4];   // [m-tile][n-tile][frag]
#pragma unroll
    for (int im = 0; im < 4; im++)
#pragma unroll
        for (int in = 0; in < 4; in++)
#pragma unroll
            for (int q = 0; q < 4; q++) acc[im][in][q] = 0.f;

    for (int kt = 0; kt < K2; kt += 32) {
        // --- A tile: 128 rows x 32 k = 1024 float4, 4 per thread ---
#pragma unroll
        for (int p = 0; p < 4; p++) {
            int f = tid + p * 256;          // 0..1023
            int r = f >> 3;                 // row 0..127
            int q = f & 7;                  // float4 index in k (k = q*4)
            int gr = rowBase + r;
            if (gr >= nRows) gr = nRows - 1;
            int kg = kt + q * 4;
            float s;
            const float* src;
            if (kg < DD) { src = Aagg + (size_t)gr * DD + kg; s = inv[gr]; }
            else         { src = Xdst + (size_t)gr * DD + (kg - DD); s = 1.0f; }
            float4 v = *(const float4*)src;
            As[r][q * 4 + 0] = f2tf32(v.x * s);
            As[r][q * 4 + 1] = f2tf32(v.y * s);
            As[r][q * 4 + 2] = f2tf32(v.z * s);
            As[r][q * 4 + 3] = f2tf32(v.w * s);
        }
        // --- B tile: 32 k x 128 cols = 1024 float4, 4 per thread ---
#pragma unroll
        for (int p = 0; p < 4; p++) {
            int f = tid + p * 256;
            int kr = f >> 5;                // k row 0..31
            int c  = f & 31;                // float4 col
            float4 v = *(const float4*)(B + (size_t)(kt + kr) * DD + c * 4);
            Bs[kr][c * 4 + 0] = f2tf32(v.x);
            Bs[kr][c * 4 + 1] = f2tf32(v.y);
            Bs[kr][c * 4 + 2] = f2tf32(v.z);
            Bs[kr][c * 4 + 3] = f2tf32(v.w);
        }
        __syncthreads();

#pragma unroll
        for (int kk = 0; kk < 32; kk += 8) {
            uint32_t a[4][4], b[4][2];
#pragma unroll
            for (int im = 0; im < 4; im++) {
                int rm = m0 + im * 16 + g;
                a[im][0] = As[rm][kk + t];
                a[im][1] = As[rm + 8][kk + t];
                a[im][2] = As[rm][kk + t + 4];
                a[im][3] = As[rm + 8][kk + t + 4];
            }
#pragma unroll
            for (int in = 0; in < 4; in++) {
                int cn = n0 + in * 8 + g;
                b[in][0] = Bs[kk + t][cn];
                b[in][1] = Bs[kk + t + 4][cn];
            }
#pragma unroll
            for (int im = 0; im < 4; im++)
#pragma unroll
                for (int in = 0; in < 4; in++) {
                    asm volatile(
                        "mma.sync.aligned.m16n8k8.row.col.f32.tf32.tf32.f32 "
                        "{%0,%1,%2,%3}, {%4,%5,%6,%7}, {%8,%9}, {%0,%1,%2,%3};"
                        : "+f"(acc[im][in][0]), "+f"(acc[im][in][1]),
                          "+f"(acc[im][in][2]), "+f"(acc[im][in][3])
                        : "r"(a[im][0]), "r"(a[im][1]), "r"(a[im][2]), "r"(a[im][3]),
                          "r"(b[in][0]), "r"(b[in][1]));
                }
        }
        __syncthreads();
    }

    // ---- epilogue: c0,c1 at (row g, col 2t), c2,c3 at (row g+8, col 2t) ----
#pragma unroll
    for (int in = 0; in < 4; in++) {
        int col = n0 + in * 8 + 2 * t;
        float b0 = bias[col], b1 = bias[col + 1];
#pragma unroll
        for (int im = 0; im < 4; im++) {
            int r0 = rowBase + m0 + im * 16 + g;
            float v0 = acc[im][in][0] + b0;
            float v1 = acc[im][in][1] + b1;
            float v2 = acc[im][in][2] + b0;
            float v3 = acc[im][in][3] + b1;
            if (relu) {
                v0 = fmaxf(v0, 0.f); v1 = fmaxf(v1, 0.f);
                v2 = fmaxf(v2, 0.f); v3 = fmaxf(v3, 0.f);
            }
            if (r0 < nRows)
                *(float2*)(Cout + (size_t)r0 * DD + col) = make_float2(v0, v1);
            if (r0 + 8 < nRows)
                *(float2*)(Cout + (size_t)(r0 + 8) * DD + col) = make_float2(v2, v3);
        }
    }
}

// ---------------- launch ----------------
extern "C" void kernel_launch(void* const* d_in, const int* in_sizes, int n_in,
                              void* d_out, int out_size) {
    const float* x_m = (const float*)d_in[0];
    const float* x_t = (const float*)d_in[1];
    const float* Wl  = (const float*)d_in[2];
    const float* bl  = (const float*)d_in[3];
    const float* Wr  = (const float*)d_in[4];
    const void*  e_mt = d_in[5];
    const void*  e_tm = d_in[6];
    float* out = (float*)d_out;

    float *agg_t, *agg_m, *bm0, *bm1, *bt0, *bt1, *inv_t, *inv_m, *Bext;
    int *e32_mt, *e32_tm;
    cudaGetSymbolAddress((void**)&agg_t, g_agg_t);
    cudaGetSymbolAddress((void**)&agg_m, g_agg_m);
    cudaGetSymbolAddress((void**)&bm0, g_bm0);
    cudaGetSymbolAddress((void**)&bm1, g_bm1);
    cudaGetSymbolAddress((void**)&bt0, g_bt0);
    cudaGetSymbolAddress((void**)&bt1, g_bt1);
    cudaGetSymbolAddress((void**)&inv_t, g_inv_t);
    cudaGetSymbolAddress((void**)&inv_m, g_inv_m);
    cudaGetSymbolAddress((void**)&Bext, g_Bext);
    cudaGetSymbolAddress((void**)&e32_mt, g_e32_mt);
    cudaGetSymbolAddress((void**)&e32_tm, g_e32_tm);

    // ---- edge dtype detection + conversion to int32 ----
    detect_reset<<<1, 1>>>();
    detect_kernel<<<256, 256>>>((const unsigned*)e_mt);
    convert_kernel<<<CDIV(2 * NE, 256), 256>>>(e_mt, e32_mt);
    convert_kernel<<<CDIV(2 * NE, 256), 256>>>(e_tm, e32_tm);

    // weight transpose/concat
    prep_weights<<<CDIV(3 * 2 * K2 * DD, 256), 256>>>(Wl, Wr, Bext);

    // per-destination inverse mean counts (edge-only, reused for all layers)
    zero_kernel<<<128, 256>>>((float4*)inv_t, NT / 4);
    zero_kernel<<<128, 256>>>((float4*)inv_m, NM / 4);
    count_kernel<<<CDIV(NE, 256), 256>>>(e32_mt, inv_t);
    count_kernel<<<CDIV(NE, 256), 256>>>(e32_tm, inv_m);
    invert_kernel<<<CDIV(NT, 256), 256>>>(inv_t, NT);
    invert_kernel<<<CDIV(NM, 256), 256>>>(inv_m, NM);

    const float* xm_cur = x_m;
    const float* xt_cur = x_t;
    float* out_m = out;
    float* out_t = out + (size_t)NM * DD;

    const int scatterBlocks = CDIV(NE * 32, 256);
    const int aggT4 = NT * DD / 4;
    const int aggM4 = NM * DD / 4;

    for (int layer = 0; layer < 3; layer++) {
        float* xt_next = (layer == 2) ? out_t : ((layer == 0) ? bt0 : bt1);
        float* xm_next = (layer == 2) ? out_m : ((layer == 0) ? bm0 : bm1);
        int relu = (layer < 2) ? 1 : 0;

        // edge type 0: musicians -> tracks
        zero_kernel<<<4096, 256>>>((float4*)agg_t, aggT4);
        scatter_kernel<<<scatterBlocks, 256>>>(xm_cur, e32_mt, agg_t);
        // edge type 1: tracks -> musicians
        zero_kernel<<<4096, 256>>>((float4*)agg_m, aggM4);
        scatter_kernel<<<scatterBlocks, 256>>>(xt_cur, e32_tm, agg_m);

        gemm_sage_tc<<<CDIV(NT, 128), 256>>>(
            agg_t, inv_t, xt_cur,
            Bext + (size_t)(layer * 2 + 0) * K2 * DD,
            bl + (size_t)(layer * 2 + 0) * DD,
            xt_next, NT, relu);
        gemm_sage_tc<<<CDIV(NM, 128), 256>>>(
            agg_m, inv_m, xm_cur,
            Bext + (size_t)(layer * 2 + 1) * K2 * DD,
            bl + (size_t)(layer * 2 + 1) * DD,
            xm_next, NM, relu);

        xm_cur = xm_next;
        xt_cur = xt_next;
    }
}